// round 2
// baseline (speedup 1.0000x reference)
#include <cuda_runtime.h>
#include <cstdint>

// UpsampleNearest4D: x (2,8,8,16,64,64) f32, scale=2 on axes 2..5.
// Output (2,8,16,32,128,128).
//
// Input-driven: one thread per input float4 (4 consecutive x values).
// Each thread writes 8 x 32B stores (st.global.v8.f32, sm_100a 256-bit STG)
// of {a,a,b,b,c,c,d,d} covering the 2x2x2x2 (t,z,y,x) duplication.
// A warp's 32 lanes cover x4=0..15 twice? No: warp covers one half... see idx map.
//
// Input geometry (collapsed): NC=16, T=8, Z=16, Y=64, X=64 floats
//   -> 16 float4 per input row; idx low 4 bits = x4, so 2 input rows per warp,
//      each STG slot writes 2 x 512B contiguous regions per warp.

__global__ __launch_bounds__(256) void upsample4d_kernel(
    const float4* __restrict__ in, char* __restrict__ out)
{
    unsigned idx = blockIdx.x * 256u + threadIdx.x;   // [0, 2097152)

    unsigned x4 = idx & 15u;            // float4 column within input row
    unsigned r  = idx >> 4;
    unsigned y  = r & 63u;  r >>= 6;
    unsigned z  = r & 15u;  r >>= 4;
    unsigned t  = r & 7u;   r >>= 3;
    unsigned nc = r;                    // [0,16)

    float4 v = __ldg(&in[idx]);

    // Offsets in 32-byte units.
    const unsigned SY = 16u;                  // one output row = 128 f32 = 512B
    const unsigned SZ = 128u * 16u;           // OY rows
    const unsigned ST = 32u * 128u * 16u;     // OZ * OY rows

    unsigned base = ((((nc * 16u + 2u * t) * 32u + 2u * z) * 128u + 2u * y) * 16u) + x4;

    unsigned off[8];
    off[0] = base;
    off[1] = base + SY;
    off[2] = base + SZ;
    off[3] = base + SZ + SY;
    off[4] = base + ST;
    off[5] = base + ST + SY;
    off[6] = base + ST + SZ;
    off[7] = base + ST + SZ + SY;

    #pragma unroll
    for (int i = 0; i < 8; i++) {
        char* p = out + (size_t)off[i] * 32u;
        asm volatile(
            "st.global.v8.f32 [%0], {%1,%2,%3,%4,%5,%6,%7,%8};"
            :: "l"(p),
               "f"(v.x), "f"(v.x), "f"(v.y), "f"(v.y),
               "f"(v.z), "f"(v.z), "f"(v.w), "f"(v.w)
            : "memory");
    }
}

extern "C" void kernel_launch(void* const* d_in, const int* in_sizes, int n_in,
                              void* d_out, int out_size)
{
    const float4* in = (const float4*)d_in[0];
    char* out = (char*)d_out;

    // 8,388,608 input floats -> 2,097,152 float4 threads
    const unsigned n_threads = 8u * 1024u * 1024u / 4u;
    upsample4d_kernel<<<n_threads / 256u, 256u>>>(in, out);
}